// round 15
// baseline (speedup 1.0000x reference)
#include <cuda_runtime.h>
#include <float.h>

typedef unsigned long long ull;

// ---------------- scratch (no allocs allowed) ----------------
__device__ float g_part0[4][10][65536];   // per-channel-group partial dists, scale0
__device__ float g_part1[4][5][16384];    // scale1 partials
__device__ float g_q[15][8][5];           // per-(target, segment) top-5
__device__ unsigned g_done = 0;

#define BIGV 1.0e30f

// packed f32x2 add (FADD2 on sm_103a)
__device__ __forceinline__ ull add2(ull a, ull b) {
    ull r;
    asm("add.rn.f32x2 %0, %1, %2;" : "=l"(r) : "l"(a), "l"(b));
    return r;
}
#define ABS2_MASK 0x7fffffff7fffffffULL

// one L1 step for a channel-pair: acc += |w + (-t)|
#define STEP(acc, wv, ntv) do { \
    ull d_ = add2((wv), (ntv)); \
    d_ &= ABS2_MASK;            \
    (acc) = add2((acc), d_);    \
} while (0)

// shared layout (fused kernel):
//   win2 : 4 cpairs x 10 rows x 66 cols of float2   = 5280 floats
//   tp   : 10 t x 8 cpairs x 10 k(pad) x 2 ch       = 1600 floats (negated tgt)
#define WIN_F2(cp, r, x)      win2[((cp) * 10 + (r)) * 66 + (x)]
#define TP_IDX(t, cpg, k, ch) ((((t) * 8 + (cpg)) * 10 + (k)) * 2 + (ch))

// ---------------- fused scale0 + scale1 kernel ---------------------------
// grid = (192, 4):  x in [0,128)   -> scale0 tile (8h x 64w patches, 2/thread)
//                   x in [128,192) -> scale1 p-block
//                   y = channel group
__global__ __launch_bounds__(256, 2) void dist_kernel(
    const float* __restrict__ src0, const float* __restrict__ tgt0,
    const int* __restrict__ pos0,
    const float* __restrict__ src1, const float* __restrict__ tgt1,
    const int* __restrict__ pos1)
{
    __shared__ __align__(16) float sraw[6880];
    const int tid = threadIdx.x;
    const int cg  = blockIdx.y;           // 0..3

    if (blockIdx.x >= 128) {
        // ================= scale 1: ps=1, C=128, 5 targets ================
        float* sT = sraw;                 // [5][32]
        const int cbase = cg * 32;
        if (tid < 160) {
            int t = tid >> 5, c = tid & 31;
            sT[t * 32 + c] =
                tgt1[(cbase + c) * 16384 + pos1[2 * t] * 128 + pos1[2 * t + 1]];
        }
        __syncthreads();

        int p = (blockIdx.x - 128) * 256 + tid;   // 0..16383
        if (p < 16129) {
            int h = p / 127, w = p - h * 127;
            const float* sp = src1 + cbase * 16384 + h * 128 + w;
            float a0 = 0, a1 = 0, a2 = 0, a3 = 0, a4 = 0;
            #pragma unroll 4
            for (int c = 0; c < 32; ++c) {
                float s = sp[c * 16384];
                a0 += fabsf(s - sT[0 * 32 + c]);
                a1 += fabsf(s - sT[1 * 32 + c]);
                a2 += fabsf(s - sT[2 * 32 + c]);
                a3 += fabsf(s - sT[3 * 32 + c]);
                a4 += fabsf(s - sT[4 * 32 + c]);
            }
            g_part1[cg][0][p] = a0; g_part1[cg][1][p] = a1;
            g_part1[cg][2][p] = a2; g_part1[cg][3][p] = a3;
            g_part1[cg][4][p] = a4;
        } else {
            g_part1[cg][0][p] = BIGV; g_part1[cg][1][p] = BIGV;
            g_part1[cg][2][p] = BIGV; g_part1[cg][3][p] = BIGV;
            g_part1[cg][4][p] = BIGV;
        }
        return;
    }

    // =============== scale 0: ps=3, C=64, 10 targets, f32x2 ==============
    float2* win2 = (float2*)sraw;
    float*  tp   = sraw + 5280;

    const int tile  = blockIdx.x;         // 0..127
    const int w0    = (tile & 3) * 64;
    const int h0    = (tile >> 2) * 8;
    const int hl    = tid >> 5;           // patch row 0..7
    const int lane  = tid & 31;
    const int w2    = lane * 2;           // patch cols w2, w2+1
    const int warp  = tid >> 5;
    const int cbase = cg * 16;

    // ---- stage NEGATED target patches: 10 t x 8 cpairs x 9 k x 2 ch ----
    if (tid < 160) {
        const int ch = tid & 1;
        const int cp = (tid >> 1) & 7;
        const int t  = tid >> 4;
        const int c  = cbase + cp * 2 + ch;
        const int th = pos0[2 * t], tw = pos0[2 * t + 1];
        const float* tg = tgt0 + c * 65536 + th * 256 + tw;
        #pragma unroll
        for (int k = 0; k < 9; ++k) {
            const int i = k / 3, j = k % 3;
            tp[TP_IDX(t, cp, k, ch)] = -tg[i * 256 + j];
        }
    }

    ull accA[10], accB[10];
    #pragma unroll
    for (int t = 0; t < 10; ++t) { accA[t] = 0ULL; accB[t] = 0ULL; }

    for (int cb = 0; cb < 16; cb += 8) {      // two window stages of 8 ch
        __syncthreads();
        // window load: 4 cpairs x 10 rows x 66 cols (channel-paired float2)
        for (int rj = warp; rj < 40; rj += 8) {
            const int cp = rj & 3;
            const int r  = rj >> 2;
            const int gy = min(h0 + r, 255);
            const float* s0 = src0 + (cbase + cb + cp * 2) * 65536 + gy * 256;
            const float* s1 = s0 + 65536;
            int gx = w0 + lane;
            WIN_F2(cp, r, lane)      = make_float2(s0[gx], s1[gx]);
            WIN_F2(cp, r, 32 + lane) = make_float2(s0[gx + 32], s1[gx + 32]);
            if (lane < 2) {
                int x = min(w0 + 64 + lane, 255);
                WIN_F2(cp, r, 64 + lane) = make_float2(s0[x], s1[x]);
            }
        }
        __syncthreads();

        #pragma unroll
        for (int cp = 0; cp < 4; ++cp) {
            const int cpg = (cb >> 1) + cp;   // 0..7
            // 3 rows x 4 cols of channel-pair window values
            ull w00 = *(const ull*)&WIN_F2(cp, hl    , w2    );
            ull w01 = *(const ull*)&WIN_F2(cp, hl    , w2 + 1);
            ull w02 = *(const ull*)&WIN_F2(cp, hl    , w2 + 2);
            ull w03 = *(const ull*)&WIN_F2(cp, hl    , w2 + 3);
            ull w10 = *(const ull*)&WIN_F2(cp, hl + 1, w2    );
            ull w11 = *(const ull*)&WIN_F2(cp, hl + 1, w2 + 1);
            ull w12 = *(const ull*)&WIN_F2(cp, hl + 1, w2 + 2);
            ull w13 = *(const ull*)&WIN_F2(cp, hl + 1, w2 + 3);
            ull w20 = *(const ull*)&WIN_F2(cp, hl + 2, w2    );
            ull w21 = *(const ull*)&WIN_F2(cp, hl + 2, w2 + 1);
            ull w22 = *(const ull*)&WIN_F2(cp, hl + 2, w2 + 2);
            ull w23 = *(const ull*)&WIN_F2(cp, hl + 2, w2 + 3);
            #pragma unroll
            for (int t = 0; t < 10; ++t) {
                const ull* nt = (const ull*)&tp[TP_IDX(t, cpg, 0, 0)];
                ull n0 = nt[0], n1 = nt[1], n2 = nt[2];
                ull n3 = nt[3], n4 = nt[4], n5 = nt[5];
                ull n6 = nt[6], n7 = nt[7], n8 = nt[8];
                ull sA = accA[t], sB = accB[t];
                STEP(sA, w00, n0);  STEP(sB, w01, n0);
                STEP(sA, w01, n1);  STEP(sB, w02, n1);
                STEP(sA, w02, n2);  STEP(sB, w03, n2);
                STEP(sA, w10, n3);  STEP(sB, w11, n3);
                STEP(sA, w11, n4);  STEP(sB, w12, n4);
                STEP(sA, w12, n5);  STEP(sB, w13, n5);
                STEP(sA, w20, n6);  STEP(sB, w21, n6);
                STEP(sA, w21, n7);  STEP(sB, w22, n7);
                STEP(sA, w22, n8);  STEP(sB, w23, n8);
                accA[t] = sA; accB[t] = sB;
            }
        }
    }

    const int h = h0 + hl;
    const int w = w0 + w2;
    const bool vA = (h < 253) && (w < 253);
    const bool vB = (h < 253) && (w + 1 < 253);
    const int idx = h * 256 + w;
    #pragma unroll
    for (int t = 0; t < 10; ++t) {
        float a = __uint_as_float((unsigned)(accA[t] & 0xffffffffULL)) +
                  __uint_as_float((unsigned)(accA[t] >> 32));
        float b = __uint_as_float((unsigned)(accB[t] & 0xffffffffULL)) +
                  __uint_as_float((unsigned)(accB[t] >> 32));
        float2 o;
        o.x = vA ? a : BIGV;
        o.y = vB ? b : BIGV;
        *(float2*)&g_part0[cg][t][idx] = o;
    }
}

// ---------------- top-5 reduce (partial-sum + top5 + final), 120 blocks ---
__device__ __forceinline__ void ins5(float v, float& m0, float& m1,
                                     float& m2, float& m3, float& m4)
{
    if (v < m4) {
        m4 = v;
        if (m4 < m3) { float x = m3; m3 = m4; m4 = x; }
        if (m3 < m2) { float x = m2; m2 = m3; m3 = x; }
        if (m2 < m1) { float x = m1; m1 = m2; m2 = x; }
        if (m1 < m0) { float x = m0; m0 = m1; m1 = x; }
    }
}

__global__ __launch_bounds__(512) void reduce_kernel(float* __restrict__ out)
{
    __shared__ float sm[512 * 5];
    const int b   = blockIdx.x;    // 0..119
    const int t   = b >> 3;        // 0..14
    const int q   = b & 7;         // segment
    const int tid = threadIdx.x;

    const float *p0, *p1, *p2, *p3;
    int N;
    if (t < 10) {
        int base = q * 8192;  N = 8192;
        p0 = &g_part0[0][t][base]; p1 = &g_part0[1][t][base];
        p2 = &g_part0[2][t][base]; p3 = &g_part0[3][t][base];
    } else {
        int base = q * 2048;  N = 2048;
        p0 = &g_part1[0][t - 10][base]; p1 = &g_part1[1][t - 10][base];
        p2 = &g_part1[2][t - 10][base]; p3 = &g_part1[3][t - 10][base];
    }

    float m0 = FLT_MAX, m1 = FLT_MAX, m2 = FLT_MAX, m3 = FLT_MAX, m4 = FLT_MAX;
    for (int i = tid; i < N; i += 512) {
        float v = (p0[i] + p1[i]) + (p2[i] + p3[i]);
        ins5(v, m0, m1, m2, m3, m4);
    }
    sm[tid * 5 + 0] = m0; sm[tid * 5 + 1] = m1; sm[tid * 5 + 2] = m2;
    sm[tid * 5 + 3] = m3; sm[tid * 5 + 4] = m4;
    __syncthreads();

    if (tid < 32) {   // 32 threads x 80 values
        float n0 = FLT_MAX, n1 = FLT_MAX, n2 = FLT_MAX, n3 = FLT_MAX, n4 = FLT_MAX;
        for (int i = tid * 80; i < tid * 80 + 80; ++i)
            ins5(sm[i], n0, n1, n2, n3, n4);
        sm[tid * 5 + 0] = n0; sm[tid * 5 + 1] = n1; sm[tid * 5 + 2] = n2;
        sm[tid * 5 + 3] = n3; sm[tid * 5 + 4] = n4;
    }
    __syncthreads();

    if (tid == 0) {
        float n0 = FLT_MAX, n1 = FLT_MAX, n2 = FLT_MAX, n3 = FLT_MAX, n4 = FLT_MAX;
        for (int i = 0; i < 160; ++i)
            ins5(sm[i], n0, n1, n2, n3, n4);
        g_q[t][q][0] = n0; g_q[t][q][1] = n1; g_q[t][q][2] = n2;
        g_q[t][q][3] = n3; g_q[t][q][4] = n4;
        __threadfence();
        unsigned v = atomicAdd(&g_done, 1u);
        if (v == 119u) {               // last block: deterministic final merge
            __threadfence();
            float s = 0.f;
            #pragma unroll
            for (int tt = 0; tt < 15; ++tt) {
                float c0 = FLT_MAX, c1 = FLT_MAX, c2 = FLT_MAX,
                      c3 = FLT_MAX, c4 = FLT_MAX;
                #pragma unroll
                for (int qq = 0; qq < 8; ++qq)
                    #pragma unroll
                    for (int k = 0; k < 5; ++k)
                        ins5(g_q[tt][qq][k], c0, c1, c2, c3, c4);
                float inv = (tt < 10) ? (1.0f / (576.0f * 5.0f))
                                      : (1.0f / (128.0f * 5.0f));
                s += (c0 + c1 + c2 + c3 + c4) * inv;
            }
            out[0] = s * 0.1f;          // / PATCH_NUM
            g_done = 0;                 // reset for next graph replay
        }
    }
}

// ---------------- launch ----------------
extern "C" void kernel_launch(void* const* d_in, const int* in_sizes, int n_in,
                              void* d_out, int out_size)
{
    const float* src0 = (const float*)d_in[0];
    const float* tgt0 = (const float*)d_in[1];
    const float* src1 = (const float*)d_in[2];
    const float* tgt1 = (const float*)d_in[3];
    const int*   pos0 = (const int*)d_in[4];
    const int*   pos1 = (const int*)d_in[5];

    dist_kernel<<<dim3(192, 4), 256>>>(src0, tgt0, pos0, src1, tgt1, pos1);
    reduce_kernel<<<120, 512>>>((float*)d_out);
}

// round 17
// speedup vs baseline: 1.1190x; 1.1190x over previous
#include <cuda_runtime.h>
#include <float.h>

typedef unsigned long long ull;

// ---------------- scratch (no allocs allowed) ----------------
__device__ float g_part0[4][10][65536];   // per-channel-group partial dists, scale0
__device__ float g_part1[4][5][16384];    // scale1 partials
__device__ float g_q[15][8][5];           // per-(target, segment) top-5
__device__ unsigned g_done = 0;

#define BIGV 1.0e30f

// packed f32x2 add (FADD2 on sm_103a)
__device__ __forceinline__ ull add2(ull a, ull b) {
    ull r;
    asm("add.rn.f32x2 %0, %1, %2;" : "=l"(r) : "l"(a), "l"(b));
    return r;
}
#define ABS2_MASK 0x7fffffff7fffffffULL

// one L1 step for a channel-pair: acc += |w + (-t)|
#define STEP(acc, wv, ntv) do { \
    ull d_ = add2((wv), (ntv)); \
    d_ &= ABS2_MASK;            \
    (acc) = add2((acc), d_);    \
} while (0)

// shared layout (fused kernel):
//   win2 : 4 cpairs x 10 rows x 66 cols of float2   = 5280 floats
//   tp   : 10 t x 8 cpairs x 10 k(pad) x 2 ch       = 1600 floats (negated tgt)
#define WIN_F2(cp, r, x)      win2[((cp) * 10 + (r)) * 66 + (x)]
#define TP_IDX(t, cpg, k, ch) ((((t) * 8 + (cpg)) * 10 + (k)) * 2 + (ch))

// ---------------- fused scale0 + scale1 kernel ---------------------------
// grid = (192, 4):  x in [0,128)   -> scale0 tile (8h x 64w patches, 2/thread)
//                   x in [128,192) -> scale1 p-block
//                   y = channel group
__global__ __launch_bounds__(256, 2) void dist_kernel(
    const float* __restrict__ src0, const float* __restrict__ tgt0,
    const int* __restrict__ pos0,
    const float* __restrict__ src1, const float* __restrict__ tgt1,
    const int* __restrict__ pos1)
{
    __shared__ __align__(16) float sraw[6880];
    const int tid = threadIdx.x;
    const int cg  = blockIdx.y;           // 0..3

    if (blockIdx.x >= 128) {
        // ================= scale 1: ps=1, C=128, 5 targets ================
        float* sT = sraw;                 // [5][32]
        const int cbase = cg * 32;
        if (tid < 160) {
            int t = tid >> 5, c = tid & 31;
            sT[t * 32 + c] =
                tgt1[(cbase + c) * 16384 + pos1[2 * t] * 128 + pos1[2 * t + 1]];
        }
        __syncthreads();

        int p = (blockIdx.x - 128) * 256 + tid;   // 0..16383
        if (p < 16129) {
            int h = p / 127, w = p - h * 127;
            const float* sp = src1 + cbase * 16384 + h * 128 + w;
            float a0 = 0, a1 = 0, a2 = 0, a3 = 0, a4 = 0;
            #pragma unroll 4
            for (int c = 0; c < 32; ++c) {
                float s = sp[c * 16384];
                a0 += fabsf(s - sT[0 * 32 + c]);
                a1 += fabsf(s - sT[1 * 32 + c]);
                a2 += fabsf(s - sT[2 * 32 + c]);
                a3 += fabsf(s - sT[3 * 32 + c]);
                a4 += fabsf(s - sT[4 * 32 + c]);
            }
            g_part1[cg][0][p] = a0; g_part1[cg][1][p] = a1;
            g_part1[cg][2][p] = a2; g_part1[cg][3][p] = a3;
            g_part1[cg][4][p] = a4;
        } else {
            g_part1[cg][0][p] = BIGV; g_part1[cg][1][p] = BIGV;
            g_part1[cg][2][p] = BIGV; g_part1[cg][3][p] = BIGV;
            g_part1[cg][4][p] = BIGV;
        }
        return;
    }

    // =============== scale 0: ps=3, C=64, 10 targets, f32x2 ==============
    float2* win2 = (float2*)sraw;
    float*  tp   = sraw + 5280;

    const int tile  = blockIdx.x;         // 0..127
    const int w0    = (tile & 3) * 64;
    const int h0    = (tile >> 2) * 8;
    const int hl    = tid >> 5;           // patch row 0..7
    const int lane  = tid & 31;
    const int w2    = lane * 2;           // patch cols w2, w2+1
    const int warp  = tid >> 5;
    const int cbase = cg * 16;

    // ---- stage NEGATED target patches: 10 t x 8 cpairs x 9 k x 2 ch ----
    if (tid < 160) {
        const int ch = tid & 1;
        const int cp = (tid >> 1) & 7;
        const int t  = tid >> 4;
        const int c  = cbase + cp * 2 + ch;
        const int th = pos0[2 * t], tw = pos0[2 * t + 1];
        const float* tg = tgt0 + c * 65536 + th * 256 + tw;
        #pragma unroll
        for (int k = 0; k < 9; ++k) {
            const int i = k / 3, j = k % 3;
            tp[TP_IDX(t, cp, k, ch)] = -tg[i * 256 + j];
        }
    }

    ull accA[10], accB[10];
    #pragma unroll
    for (int t = 0; t < 10; ++t) { accA[t] = 0ULL; accB[t] = 0ULL; }

    for (int cb = 0; cb < 16; cb += 8) {      // two window stages of 8 ch
        __syncthreads();
        // window load: 4 cpairs x 10 rows x 66 cols (channel-paired float2)
        for (int rj = warp; rj < 40; rj += 8) {
            const int cp = rj & 3;
            const int r  = rj >> 2;
            const int gy = min(h0 + r, 255);
            const float* s0 = src0 + (cbase + cb + cp * 2) * 65536 + gy * 256;
            const float* s1 = s0 + 65536;
            int gx = w0 + lane;
            WIN_F2(cp, r, lane)      = make_float2(s0[gx], s1[gx]);
            WIN_F2(cp, r, 32 + lane) = make_float2(s0[gx + 32], s1[gx + 32]);
            if (lane < 2) {
                int x = min(w0 + 64 + lane, 255);
                WIN_F2(cp, r, 64 + lane) = make_float2(s0[x], s1[x]);
            }
        }
        __syncthreads();

        #pragma unroll
        for (int cp = 0; cp < 4; ++cp) {
            const int cpg = (cb >> 1) + cp;   // 0..7
            // 3 rows x 4 cols of channel-pair window values
            ull w00 = *(const ull*)&WIN_F2(cp, hl    , w2    );
            ull w01 = *(const ull*)&WIN_F2(cp, hl    , w2 + 1);
            ull w02 = *(const ull*)&WIN_F2(cp, hl    , w2 + 2);
            ull w03 = *(const ull*)&WIN_F2(cp, hl    , w2 + 3);
            ull w10 = *(const ull*)&WIN_F2(cp, hl + 1, w2    );
            ull w11 = *(const ull*)&WIN_F2(cp, hl + 1, w2 + 1);
            ull w12 = *(const ull*)&WIN_F2(cp, hl + 1, w2 + 2);
            ull w13 = *(const ull*)&WIN_F2(cp, hl + 1, w2 + 3);
            ull w20 = *(const ull*)&WIN_F2(cp, hl + 2, w2    );
            ull w21 = *(const ull*)&WIN_F2(cp, hl + 2, w2 + 1);
            ull w22 = *(const ull*)&WIN_F2(cp, hl + 2, w2 + 2);
            ull w23 = *(const ull*)&WIN_F2(cp, hl + 2, w2 + 3);
            #pragma unroll
            for (int t = 0; t < 10; ++t) {
                const ull* nt = (const ull*)&tp[TP_IDX(t, cpg, 0, 0)];
                ull n0 = nt[0], n1 = nt[1], n2 = nt[2];
                ull n3 = nt[3], n4 = nt[4], n5 = nt[5];
                ull n6 = nt[6], n7 = nt[7], n8 = nt[8];
                ull sA = accA[t], sB = accB[t];
                STEP(sA, w00, n0);  STEP(sB, w01, n0);
                STEP(sA, w01, n1);  STEP(sB, w02, n1);
                STEP(sA, w02, n2);  STEP(sB, w03, n2);
                STEP(sA, w10, n3);  STEP(sB, w11, n3);
                STEP(sA, w11, n4);  STEP(sB, w12, n4);
                STEP(sA, w12, n5);  STEP(sB, w13, n5);
                STEP(sA, w20, n6);  STEP(sB, w21, n6);
                STEP(sA, w21, n7);  STEP(sB, w22, n7);
                STEP(sA, w22, n8);  STEP(sB, w23, n8);
                accA[t] = sA; accB[t] = sB;
            }
        }
    }

    const int h = h0 + hl;
    const int w = w0 + w2;
    const bool vA = (h < 253) && (w < 253);
    const bool vB = (h < 253) && (w + 1 < 253);
    const int idx = h * 256 + w;
    #pragma unroll
    for (int t = 0; t < 10; ++t) {
        float a = __uint_as_float((unsigned)(accA[t] & 0xffffffffULL)) +
                  __uint_as_float((unsigned)(accA[t] >> 32));
        float b = __uint_as_float((unsigned)(accB[t] & 0xffffffffULL)) +
                  __uint_as_float((unsigned)(accB[t] >> 32));
        float2 o;
        o.x = vA ? a : BIGV;
        o.y = vB ? b : BIGV;
        *(float2*)&g_part0[cg][t][idx] = o;
    }
}

// ---------------- branchless sorted-5 insertion (10 FMNMX, no branches) --
__device__ __forceinline__ void ins5(float v, float& m0, float& m1,
                                     float& m2, float& m3, float& m4)
{
    float t;
    t  = fminf(m0, v);  v  = fmaxf(m0, v);  m0 = t;
    t  = fminf(m1, v);  v  = fmaxf(m1, v);  m1 = t;
    t  = fminf(m2, v);  v  = fmaxf(m2, v);  m2 = t;
    t  = fminf(m3, v);  v  = fmaxf(m3, v);  m3 = t;
    m4 = fminf(m4, v);
}

// ---------------- top-5 reduce (partial-sum + top5 + final), 120 blocks ---
__global__ __launch_bounds__(512) void reduce_kernel(float* __restrict__ out)
{
    __shared__ float sm[512 * 5];
    __shared__ float sq[600];        // staged g_q for the final merge
    __shared__ float scontrib[16];
    __shared__ int   slast;
    const int b   = blockIdx.x;    // 0..119
    const int t   = b >> 3;        // 0..14
    const int q   = b & 7;         // segment
    const int tid = threadIdx.x;

    const float4 *p0, *p1, *p2, *p3;
    int N4;
    if (t < 10) {
        int base = q * 8192;  N4 = 2048;
        p0 = (const float4*)&g_part0[0][t][base];
        p1 = (const float4*)&g_part0[1][t][base];
        p2 = (const float4*)&g_part0[2][t][base];
        p3 = (const float4*)&g_part0[3][t][base];
    } else {
        int base = q * 2048;  N4 = 512;
        p0 = (const float4*)&g_part1[0][t - 10][base];
        p1 = (const float4*)&g_part1[1][t - 10][base];
        p2 = (const float4*)&g_part1[2][t - 10][base];
        p3 = (const float4*)&g_part1[3][t - 10][base];
    }

    float m0 = FLT_MAX, m1 = FLT_MAX, m2 = FLT_MAX, m3 = FLT_MAX, m4 = FLT_MAX;
    for (int i = tid; i < N4; i += 512) {
        float4 a = p0[i], bb = p1[i], c = p2[i], d = p3[i];
        ins5((a.x + bb.x) + (c.x + d.x), m0, m1, m2, m3, m4);
        ins5((a.y + bb.y) + (c.y + d.y), m0, m1, m2, m3, m4);
        ins5((a.z + bb.z) + (c.z + d.z), m0, m1, m2, m3, m4);
        ins5((a.w + bb.w) + (c.w + d.w), m0, m1, m2, m3, m4);
    }
    sm[tid * 5 + 0] = m0; sm[tid * 5 + 1] = m1; sm[tid * 5 + 2] = m2;
    sm[tid * 5 + 3] = m3; sm[tid * 5 + 4] = m4;
    __syncthreads();

    // stage 2: 32 threads x 80 values (all threads hit the barriers below)
    if (tid < 32) {
        float n0 = FLT_MAX, n1 = FLT_MAX, n2 = FLT_MAX, n3 = FLT_MAX, n4 = FLT_MAX;
        for (int i = tid * 80; i < tid * 80 + 80; ++i)
            ins5(sm[i], n0, n1, n2, n3, n4);
        sm[tid * 5 + 0] = n0; sm[tid * 5 + 1] = n1; sm[tid * 5 + 2] = n2;
        sm[tid * 5 + 3] = n3; sm[tid * 5 + 4] = n4;
    }
    __syncthreads();

    // stage 3: thread 0 merges 160 smem values, publishes segment top-5
    if (tid == 0) {
        float c0 = FLT_MAX, c1 = FLT_MAX, c2 = FLT_MAX, c3 = FLT_MAX, c4 = FLT_MAX;
        for (int i = 0; i < 160; ++i)
            ins5(sm[i], c0, c1, c2, c3, c4);
        g_q[t][q][0] = c0; g_q[t][q][1] = c1; g_q[t][q][2] = c2;
        g_q[t][q][3] = c3; g_q[t][q][4] = c4;
        __threadfence();
        unsigned v = atomicAdd(&g_done, 1u);
        slast = (v == 119u) ? 1 : 0;
    }
    __syncthreads();

    // -------- last block: cooperative deterministic final merge --------
    if (slast) {
        const float* gq = &g_q[0][0][0];
        for (int i = tid; i < 600; i += 512) sq[i] = gq[i];   // parallel stage
        __syncthreads();
        if (tid < 15) {   // one thread per target: merge its 8 segments x 5
            float c0 = FLT_MAX, c1 = FLT_MAX, c2 = FLT_MAX,
                  c3 = FLT_MAX, c4 = FLT_MAX;
            #pragma unroll
            for (int i = 0; i < 40; ++i)
                ins5(sq[tid * 40 + i], c0, c1, c2, c3, c4);
            float inv = (tid < 10) ? (1.0f / (576.0f * 5.0f))
                                   : (1.0f / (128.0f * 5.0f));
            scontrib[tid] = (c0 + c1 + c2 + c3 + c4) * inv;
        }
        __syncthreads();
        if (tid == 0) {
            float s = 0.f;
            #pragma unroll
            for (int i = 0; i < 15; ++i) s += scontrib[i];   // fixed order
            out[0] = s * 0.1f;          // / PATCH_NUM
            g_done = 0;                 // reset for next graph replay
        }
    }
}

// ---------------- launch ----------------
extern "C" void kernel_launch(void* const* d_in, const int* in_sizes, int n_in,
                              void* d_out, int out_size)
{
    const float* src0 = (const float*)d_in[0];
    const float* tgt0 = (const float*)d_in[1];
    const float* src1 = (const float*)d_in[2];
    const float* tgt1 = (const float*)d_in[3];
    const int*   pos0 = (const int*)d_in[4];
    const int*   pos1 = (const int*)d_in[5];

    dist_kernel<<<dim3(192, 4), 256>>>(src0, tgt0, pos0, src1, tgt1, pos1);
    reduce_kernel<<<120, 512>>>((float*)d_out);
}